// round 4
// baseline (speedup 1.0000x reference)
#include <cuda_runtime.h>
#include <cuda_bf16.h>
#include <math.h>

// ---------------------------------------------------------------------------
// Problem constants
// ---------------------------------------------------------------------------
#define BATCH   4
#define SEQ     2048
#define HEADS   16
#define DHEAD   64
#define DMODEL  1024
#define NEG_BIG 1e10f

// Scratch for projected Q/K/V in [B, H, S, 64] layout (33.5 MB each).
__device__ float g_Qp[BATCH * HEADS * SEQ * DHEAD];
__device__ float g_Kp[BATCH * HEADS * SEQ * DHEAD];
__device__ float g_Vp[BATCH * HEADS * SEQ * DHEAD];

// ---------------------------------------------------------------------------
// Projection GEMM:  Out[b,h,s,d] = scale * sum_k X[b*S+s, k] * W[k, h*64+d]
// M = 8192, N = 1024, K = 1024.  128x128 block tile, 8x8 micro, Ktile = 16.
// ---------------------------------------------------------------------------
__global__ __launch_bounds__(256, 2)
void proj_gemm(const float* __restrict__ X, const float* __restrict__ W,
               float* __restrict__ Out, float scale)
{
    __shared__ float As[16][132];   // [k][m], padded (132%32=4) for store spread
    __shared__ float Bs[16][128];   // [k][n]

    const int t  = threadIdx.x;
    const int tx = t & 15;          // n direction
    const int ty = t >> 4;          // m direction
    const int m0 = blockIdx.y * 128;
    const int n0 = blockIdx.x * 128;

    float acc[8][8];
#pragma unroll
    for (int i = 0; i < 8; i++)
#pragma unroll
        for (int j = 0; j < 8; j++) acc[i][j] = 0.0f;

    for (int k0 = 0; k0 < DMODEL; k0 += 16) {
        // A tile: 128 rows x 16 k  (512 float4)
#pragma unroll
        for (int f = t; f < 512; f += 256) {
            int r  = f >> 2;
            int c4 = f & 3;
            float4 v = *(const float4*)&X[(size_t)(m0 + r) * DMODEL + k0 + c4 * 4];
            As[c4 * 4 + 0][r] = v.x;
            As[c4 * 4 + 1][r] = v.y;
            As[c4 * 4 + 2][r] = v.z;
            As[c4 * 4 + 3][r] = v.w;
        }
        // B tile: 16 k x 128 n  (512 float4)
#pragma unroll
        for (int f = t; f < 512; f += 256) {
            int r  = f >> 5;
            int c4 = f & 31;
            *(float4*)&Bs[r][c4 * 4] =
                *(const float4*)&W[(size_t)(k0 + r) * DMODEL + n0 + c4 * 4];
        }
        __syncthreads();

#pragma unroll
        for (int kk = 0; kk < 16; kk++) {
            float a[8], b[8];
            *(float4*)&a[0] = *(float4*)&As[kk][ty * 8];
            *(float4*)&a[4] = *(float4*)&As[kk][ty * 8 + 4];
            *(float4*)&b[0] = *(float4*)&Bs[kk][tx * 8];
            *(float4*)&b[4] = *(float4*)&Bs[kk][tx * 8 + 4];
#pragma unroll
            for (int i = 0; i < 8; i++)
#pragma unroll
                for (int j = 0; j < 8; j++)
                    acc[i][j] = fmaf(a[i], b[j], acc[i][j]);
        }
        __syncthreads();
    }

    // Scatter into [B, H, S, 64]
#pragma unroll
    for (int i = 0; i < 8; i++) {
        int m = m0 + ty * 8 + i;
        int b = m >> 11;            // m / 2048
        int s = m & 2047;
#pragma unroll
        for (int j = 0; j < 8; j++) {
            int n = n0 + tx * 8 + j;
            int h = n >> 6;
            int d = n & 63;
            Out[((((size_t)b * HEADS + h) * SEQ) + s) * DHEAD + d] = acc[i][j] * scale;
        }
    }
}

// ---------------------------------------------------------------------------
// Flash attention: one block = (b, h, 64-row Q tile). 256 threads, 4x4 micro.
// Q already scaled by 1/sqrt(64). Online softmax with running (m, l).
// ---------------------------------------------------------------------------
#define BQ 64
#define BK 64
#define ST 68        // smem row stride (floats); 68*4 bytes keeps float4 align

__global__ __launch_bounds__(256, 2)
void attn_kernel(const float* __restrict__ Qp, const float* __restrict__ Kp,
                 const float* __restrict__ Vp, const float* __restrict__ vmask,
                 const float* __restrict__ qmask, float* __restrict__ out)
{
    extern __shared__ float sm[];
    float* Qs  = sm;                    // [BQ][ST]  row-major  [q][kdim]
    float* Ks  = Qs  + BQ * ST;         // [DHEAD][ST] transposed: [kdim][kcol]
    float* Vs  = Ks  + BK * ST;         // [BK][ST]  natural: [krow][d]
    float* Ps  = Vs  + BK * ST;         // [BQ][ST]  scores / probs
    float* rm  = Ps  + BQ * ST;         // [BQ] running max
    float* rl  = rm  + BQ;              // [BQ] running sum
    float* ral = rl  + BQ;              // [BQ] alpha (rescale factor)
    float* vmk = ral + BQ;              // [BK] key mask tile

    const int qb = blockIdx.x;
    const int h  = blockIdx.y;
    const int b  = blockIdx.z;
    const int t  = threadIdx.x;
    const int tx = t & 15;
    const int ty = t >> 4;
    const int r0 = ty * 4;              // q rows owned by this thread
    const int c0 = tx * 4;              // k cols / d cols owned

    const size_t bh_base = ((size_t)b * HEADS + h) * SEQ;
    const float* Qg = Qp + (bh_base + (size_t)qb * BQ) * DHEAD;

    // Load Q tile (coalesced float4), init stats
#pragma unroll
    for (int f = t; f < BQ * DHEAD / 4; f += 256) {
        int r  = f >> 4;                // DHEAD/4 = 16 float4 per row
        int c4 = f & 15;
        *(float4*)&Qs[r * ST + c4 * 4] = ((const float4*)Qg)[f];
    }
    if (t < BQ) { rm[t] = -INFINITY; rl[t] = 0.0f; }

    float o[4][4];
#pragma unroll
    for (int i = 0; i < 4; i++)
#pragma unroll
        for (int j = 0; j < 4; j++) o[i][j] = 0.0f;

    for (int kb = 0; kb <= qb; kb++) {
        __syncthreads();   // previous iteration done reading Ks/Vs/Ps

        const float* Kg = Kp + (bh_base + (size_t)kb * BK) * DHEAD;
        const float* Vg = Vp + (bh_base + (size_t)kb * BK) * DHEAD;
#pragma unroll
        for (int f = t; f < BK * DHEAD / 4; f += 256) {
            int r  = f >> 4;
            int c4 = f & 15;
            float4 kv = ((const float4*)Kg)[f];
            Ks[(c4 * 4 + 0) * ST + r] = kv.x;     // transposed store
            Ks[(c4 * 4 + 1) * ST + r] = kv.y;
            Ks[(c4 * 4 + 2) * ST + r] = kv.z;
            Ks[(c4 * 4 + 3) * ST + r] = kv.w;
            *(float4*)&Vs[r * ST + c4 * 4] = ((const float4*)Vg)[f];
        }
        if (t < BK) vmk[t] = vmask[(size_t)b * SEQ + kb * BK + t];
        __syncthreads();

        // S = Q K^T  (scale already folded into Q)
        float s[4][4];
#pragma unroll
        for (int i = 0; i < 4; i++)
#pragma unroll
            for (int j = 0; j < 4; j++) s[i][j] = 0.0f;

#pragma unroll 4
        for (int kk = 0; kk < DHEAD; kk++) {
            float qv[4], kv[4];
#pragma unroll
            for (int i = 0; i < 4; i++) qv[i] = Qs[(r0 + i) * ST + kk];
#pragma unroll
            for (int j = 0; j < 4; j++) kv[j] = Ks[kk * ST + c0 + j];
#pragma unroll
            for (int i = 0; i < 4; i++)
#pragma unroll
                for (int j = 0; j < 4; j++)
                    s[i][j] = fmaf(qv[i], kv[j], s[i][j]);
        }

        // masks + stage raw scores
#pragma unroll
        for (int i = 0; i < 4; i++) {
            int gq = qb * BQ + r0 + i;
#pragma unroll
            for (int j = 0; j < 4; j++) {
                int gk = kb * BK + c0 + j;
                float sv = s[i][j] - (1.0f - vmk[c0 + j]) * NEG_BIG;
                if (gk > gq) sv -= NEG_BIG;
                Ps[(r0 + i) * ST + c0 + j] = sv;
            }
        }
        __syncthreads();

        // online softmax per row (one thread per row)
        if (t < BQ) {
            float mo = rm[t];
            float mx = mo;
#pragma unroll 8
            for (int c = 0; c < BK; c++) mx = fmaxf(mx, Ps[t * ST + c]);
            float al = __expf(mo - mx);        // exp(-inf)=0 on first tile
            float sum = 0.0f;
#pragma unroll 8
            for (int c = 0; c < BK; c++) {
                float p = __expf(Ps[t * ST + c] - mx);
                Ps[t * ST + c] = p;
                sum += p;
            }
            rm[t]  = mx;
            rl[t]  = rl[t] * al + sum;
            ral[t] = al;
        }
        __syncthreads();

        // O = alpha*O + P V
        float ai[4];
#pragma unroll
        for (int i = 0; i < 4; i++) ai[i] = ral[r0 + i];
#pragma unroll
        for (int i = 0; i < 4; i++)
#pragma unroll
            for (int j = 0; j < 4; j++) o[i][j] *= ai[i];

#pragma unroll 4
        for (int kk = 0; kk < BK; kk++) {
            float pv[4], vv[4];
#pragma unroll
            for (int i = 0; i < 4; i++) pv[i] = Ps[(r0 + i) * ST + kk];
#pragma unroll
            for (int j = 0; j < 4; j++) vv[j] = Vs[kk * ST + c0 + j];
#pragma unroll
            for (int i = 0; i < 4; i++)
#pragma unroll
                for (int j = 0; j < 4; j++)
                    o[i][j] = fmaf(pv[i], vv[j], o[i][j]);
        }
    }

    // Epilogue: normalize, apply query mask, write [B, Sq, H*64]
#pragma unroll
    for (int i = 0; i < 4; i++) {
        int gq = qb * BQ + r0 + i;
        float f = (1.0f / rl[r0 + i]) * qmask[(size_t)b * SEQ + gq];
        float4 v;
        v.x = o[i][0] * f; v.y = o[i][1] * f; v.z = o[i][2] * f; v.w = o[i][3] * f;
        *(float4*)&out[((size_t)b * SEQ + gq) * (HEADS * DHEAD) + h * DHEAD + c0] = v;
    }
}

// ---------------------------------------------------------------------------
// Launch
// ---------------------------------------------------------------------------
extern "C" void kernel_launch(void* const* d_in, const int* in_sizes, int n_in,
                              void* d_out, int out_size)
{
    const float* q     = (const float*)d_in[0];
    const float* k     = (const float*)d_in[1];
    const float* v     = (const float*)d_in[2];
    const float* vmask = (const float*)d_in[3];
    const float* qmask = (const float*)d_in[4];
    const float* Wq    = (const float*)d_in[5];
    const float* Wk    = (const float*)d_in[6];
    const float* Wv    = (const float*)d_in[7];
    float* out = (float*)d_out;

    float *qp, *kp, *vp;
    cudaGetSymbolAddress((void**)&qp, g_Qp);
    cudaGetSymbolAddress((void**)&kp, g_Kp);
    cudaGetSymbolAddress((void**)&vp, g_Vp);

    dim3 gg(DMODEL / 128, (BATCH * SEQ) / 128);   // (8, 64)
    proj_gemm<<<gg, 256>>>(q, Wq, qp, 0.125f);    // fold 1/sqrt(64) into Q
    proj_gemm<<<gg, 256>>>(k, Wk, kp, 1.0f);
    proj_gemm<<<gg, 256>>>(v, Wv, vp, 1.0f);

    const int smem_bytes = (4 * BQ * ST + 4 * BQ) * (int)sizeof(float); // ~70.7 KB
    cudaFuncSetAttribute(attn_kernel, cudaFuncAttributeMaxDynamicSharedMemorySize,
                         smem_bytes);
    dim3 ga(SEQ / BQ, HEADS, BATCH);              // (32, 16, 4)
    attn_kernel<<<ga, 256, smem_bytes>>>(qp, kp, vp, vmask, qmask, out);
}

// round 5
// speedup vs baseline: 1.1346x; 1.1346x over previous
#include <cuda_runtime.h>
#include <cuda_bf16.h>
#include <math.h>

// ---------------------------------------------------------------------------
// Problem constants
// ---------------------------------------------------------------------------
#define BATCH   4
#define SEQ     2048
#define HEADS   16
#define DHEAD   64
#define DMODEL  1024
#define NEG_BIG 1e10f

// Scratch for projected Q/K/V in [B, H, S, 64] layout (33.5 MB each).
__device__ float g_Qp[BATCH * HEADS * SEQ * DHEAD];
__device__ float g_Kp[BATCH * HEADS * SEQ * DHEAD];
__device__ float g_Vp[BATCH * HEADS * SEQ * DHEAD];

// ---------------------------------------------------------------------------
// Packed f32x2 helpers (SASS FFMA2 — double-rate fp32, PTX-only per B300 docs)
// ---------------------------------------------------------------------------
typedef unsigned long long u64;

__device__ __forceinline__ u64 pack_dup(float x) {
    u64 r;
    asm("mov.b64 %0, {%1, %1};" : "=l"(r) : "f"(x));
    return r;
}
__device__ __forceinline__ void ffma2(u64& d, u64 a, u64 b) {
    asm("fma.rn.f32x2 %0, %1, %2, %0;" : "+l"(d) : "l"(a), "l"(b));
}
__device__ __forceinline__ void fmul2(u64& d, u64 a) {
    asm("mul.rn.f32x2 %0, %0, %1;" : "+l"(d) : "l"(a));
}
__device__ __forceinline__ float2 unpack2(u64 v) {
    float2 f;
    asm("mov.b64 {%0, %1}, %2;" : "=f"(f.x), "=f"(f.y) : "l"(v));
    return f;
}

// ---------------------------------------------------------------------------
// Fused projection GEMMs:  Out[b,h,s,d] = scale * X[b*S+s,:] @ W[:, h*64+d]
// M = 8192, N = 1024, K = 1024. 128x128 block, 8x8 micro (f32x2 packed).
// blockIdx.z selects which of the 3 projections this block computes.
// ---------------------------------------------------------------------------
__global__ __launch_bounds__(256, 2)
void proj_gemm3(const float* __restrict__ Xq, const float* __restrict__ Xk,
                const float* __restrict__ Xv,
                const float* __restrict__ Wq, const float* __restrict__ Wk,
                const float* __restrict__ Wv,
                float* __restrict__ Oq, float* __restrict__ Ok,
                float* __restrict__ Ov)
{
    __shared__ float As[16][132];   // [k][m], padded for store spread
    __shared__ float Bs[16][128];   // [k][n]

    const float* X; const float* W; float* Out; float scale;
    if (blockIdx.z == 0)      { X = Xq; W = Wq; Out = Oq; scale = 0.125f; }
    else if (blockIdx.z == 1) { X = Xk; W = Wk; Out = Ok; scale = 1.0f;   }
    else                      { X = Xv; W = Wv; Out = Ov; scale = 1.0f;   }

    const int t  = threadIdx.x;
    const int tx = t & 15;          // n direction
    const int ty = t >> 4;          // m direction
    const int m0 = blockIdx.y * 128;
    const int n0 = blockIdx.x * 128;

    u64 acc2[8][4];
#pragma unroll
    for (int i = 0; i < 8; i++)
#pragma unroll
        for (int j = 0; j < 4; j++) acc2[i][j] = 0ull;

    for (int k0 = 0; k0 < DMODEL; k0 += 16) {
        // A tile: 128 rows x 16 k  (512 float4), transposed store
#pragma unroll
        for (int f = t; f < 512; f += 256) {
            int r  = f >> 2;
            int c4 = f & 3;
            float4 v = *(const float4*)&X[(size_t)(m0 + r) * DMODEL + k0 + c4 * 4];
            As[c4 * 4 + 0][r] = v.x;
            As[c4 * 4 + 1][r] = v.y;
            As[c4 * 4 + 2][r] = v.z;
            As[c4 * 4 + 3][r] = v.w;
        }
        // B tile: 16 k x 128 n  (512 float4)
#pragma unroll
        for (int f = t; f < 512; f += 256) {
            int r  = f >> 5;
            int c4 = f & 31;
            *(float4*)&Bs[r][c4 * 4] =
                *(const float4*)&W[(size_t)(k0 + r) * DMODEL + n0 + c4 * 4];
        }
        __syncthreads();

#pragma unroll
        for (int kk = 0; kk < 16; kk++) {
            float4 a0 = *(float4*)&As[kk][ty * 8];
            float4 a1 = *(float4*)&As[kk][ty * 8 + 4];
            ulonglong2 b01 = *(ulonglong2*)&Bs[kk][tx * 8];
            ulonglong2 b23 = *(ulonglong2*)&Bs[kk][tx * 8 + 4];
            u64 ad[8];
            ad[0] = pack_dup(a0.x); ad[1] = pack_dup(a0.y);
            ad[2] = pack_dup(a0.z); ad[3] = pack_dup(a0.w);
            ad[4] = pack_dup(a1.x); ad[5] = pack_dup(a1.y);
            ad[6] = pack_dup(a1.z); ad[7] = pack_dup(a1.w);
#pragma unroll
            for (int i = 0; i < 8; i++) {
                ffma2(acc2[i][0], ad[i], b01.x);
                ffma2(acc2[i][1], ad[i], b01.y);
                ffma2(acc2[i][2], ad[i], b23.x);
                ffma2(acc2[i][3], ad[i], b23.y);
            }
        }
        __syncthreads();
    }

    // Scatter into [B, H, S, 64]
#pragma unroll
    for (int i = 0; i < 8; i++) {
        int m = m0 + ty * 8 + i;
        int b = m >> 11;            // m / 2048
        int s = m & 2047;
#pragma unroll
        for (int j2 = 0; j2 < 4; j2++) {
            float2 v = unpack2(acc2[i][j2]);
            int n = n0 + tx * 8 + j2 * 2;
            int h0 = n >> 6, d0 = n & 63;
            int h1 = (n + 1) >> 6, d1 = (n + 1) & 63;
            Out[((((size_t)b * HEADS + h0) * SEQ) + s) * DHEAD + d0] = v.x * scale;
            Out[((((size_t)b * HEADS + h1) * SEQ) + s) * DHEAD + d1] = v.y * scale;
        }
    }
}

// ---------------------------------------------------------------------------
// Flash attention: one block = (b, h, 64-row Q tile). 256 threads, 4x4 micro.
// All inner-loop smem operands vectorized; softmax in registers via shuffles.
// ---------------------------------------------------------------------------
#define BQ 64
#define BK 64
#define ST 68        // smem row stride (floats); 68*4B is 16B-aligned, 68%32=4

__global__ __launch_bounds__(256, 2)
void attn_kernel(const float* __restrict__ Qp, const float* __restrict__ Kp,
                 const float* __restrict__ Vp, const float* __restrict__ vmask,
                 const float* __restrict__ qmask, float* __restrict__ out)
{
    extern __shared__ float sm[];
    float* Qs  = sm;                    // [DHEAD][ST] transposed: [d][qrow]
    float* Ks  = Qs  + DHEAD * ST;      // [DHEAD][ST] transposed: [d][kcol]
    float* Vs  = Ks  + DHEAD * ST;      // [BK][ST]   natural:     [krow][d]
    float* Ps  = Vs  + BK * ST;         // [BK][ST]   transposed:  [krow][qrow]
    float* vmk = Ps  + BK * ST;         // [BK] key mask tile

    const int qb = blockIdx.x;
    const int h  = blockIdx.y;
    const int b  = blockIdx.z;
    const int t  = threadIdx.x;
    const int tx = t & 15;              // k-col / d-col group (within half-warp)
    const int ty = t >> 4;              // q-row group
    const int r0 = ty * 4;
    const int c0 = tx * 4;

    const size_t bh_base = ((size_t)b * HEADS + h) * SEQ;
    const float* Qg = Qp + (bh_base + (size_t)qb * BQ) * DHEAD;

    // Load Q tile transposed into Qs[d][q]
#pragma unroll
    for (int f = t; f < BQ * DHEAD / 4; f += 256) {
        int r  = f >> 4;                // q row
        int c4 = f & 15;
        float4 qv = ((const float4*)Qg)[f];
        Qs[(c4 * 4 + 0) * ST + r] = qv.x;
        Qs[(c4 * 4 + 1) * ST + r] = qv.y;
        Qs[(c4 * 4 + 2) * ST + r] = qv.z;
        Qs[(c4 * 4 + 3) * ST + r] = qv.w;
    }

    float m_run[4], l_run[4];
#pragma unroll
    for (int i = 0; i < 4; i++) { m_run[i] = -INFINITY; l_run[i] = 0.0f; }

    u64 o2[4][2];
#pragma unroll
    for (int i = 0; i < 4; i++) { o2[i][0] = 0ull; o2[i][1] = 0ull; }

    for (int kb = 0; kb <= qb; kb++) {
        __syncthreads();   // previous iteration done reading Ks/Vs/Ps

        const float* Kg = Kp + (bh_base + (size_t)kb * BK) * DHEAD;
        const float* Vg = Vp + (bh_base + (size_t)kb * BK) * DHEAD;
#pragma unroll
        for (int f = t; f < BK * DHEAD / 4; f += 256) {
            int r  = f >> 4;
            int c4 = f & 15;
            float4 kv = ((const float4*)Kg)[f];
            Ks[(c4 * 4 + 0) * ST + r] = kv.x;     // transposed store
            Ks[(c4 * 4 + 1) * ST + r] = kv.y;
            Ks[(c4 * 4 + 2) * ST + r] = kv.z;
            Ks[(c4 * 4 + 3) * ST + r] = kv.w;
            *(float4*)&Vs[r * ST + c4 * 4] = ((const float4*)Vg)[f];
        }
        if (t < BK) vmk[t] = vmask[(size_t)b * SEQ + kb * BK + t];
        __syncthreads();

        // ---- S = Q K^T (scale folded into Q), packed f32x2 accumulators ----
        u64 s2[4][2];
#pragma unroll
        for (int i = 0; i < 4; i++) { s2[i][0] = 0ull; s2[i][1] = 0ull; }

#pragma unroll 8
        for (int kk = 0; kk < DHEAD; kk++) {
            float4 qv = *(const float4*)&Qs[kk * ST + r0];   // broadcast in group
            ulonglong2 kp = *(const ulonglong2*)&Ks[kk * ST + c0];
            u64 q0 = pack_dup(qv.x), q1 = pack_dup(qv.y);
            u64 q2 = pack_dup(qv.z), q3 = pack_dup(qv.w);
            ffma2(s2[0][0], q0, kp.x); ffma2(s2[0][1], q0, kp.y);
            ffma2(s2[1][0], q1, kp.x); ffma2(s2[1][1], q1, kp.y);
            ffma2(s2[2][0], q2, kp.x); ffma2(s2[2][1], q2, kp.y);
            ffma2(s2[3][0], q3, kp.x); ffma2(s2[3][1], q3, kp.y);
        }

        // unpack + masks (registers)
        float sv[4][4];
        float vm0 = (1.0f - vmk[c0 + 0]) * NEG_BIG;
        float vm1 = (1.0f - vmk[c0 + 1]) * NEG_BIG;
        float vm2 = (1.0f - vmk[c0 + 2]) * NEG_BIG;
        float vm3 = (1.0f - vmk[c0 + 3]) * NEG_BIG;
#pragma unroll
        for (int i = 0; i < 4; i++) {
            float2 lo = unpack2(s2[i][0]);
            float2 hi = unpack2(s2[i][1]);
            sv[i][0] = lo.x - vm0; sv[i][1] = lo.y - vm1;
            sv[i][2] = hi.x - vm2; sv[i][3] = hi.y - vm3;
        }
        if (kb == qb) {  // causal only matters on the diagonal tile
#pragma unroll
            for (int i = 0; i < 4; i++)
#pragma unroll
                for (int j = 0; j < 4; j++)
                    if (c0 + j > r0 + i) sv[i][j] -= NEG_BIG;
        }

        // ---- online softmax in registers (reduce across the 16-lane group) ----
        float p[4][4], alpha[4];
#pragma unroll
        for (int i = 0; i < 4; i++) {
            float mx = fmaxf(fmaxf(sv[i][0], sv[i][1]), fmaxf(sv[i][2], sv[i][3]));
#pragma unroll
            for (int off = 1; off < 16; off <<= 1)
                mx = fmaxf(mx, __shfl_xor_sync(0xffffffffu, mx, off));
            float mnew = fmaxf(m_run[i], mx);
            alpha[i] = __expf(m_run[i] - mnew);   // exp(-inf)=0 on first tile
            m_run[i] = mnew;
            float sum = 0.0f;
#pragma unroll
            for (int j = 0; j < 4; j++) {
                p[i][j] = __expf(sv[i][j] - mnew);
                sum += p[i][j];
            }
#pragma unroll
            for (int off = 1; off < 16; off <<= 1)
                sum += __shfl_xor_sync(0xffffffffu, sum, off);
            l_run[i] = l_run[i] * alpha[i] + sum;
        }

        // stage P transposed: Ps[kcol][qrow]
#pragma unroll
        for (int j = 0; j < 4; j++) {
            float4 pj = make_float4(p[0][j], p[1][j], p[2][j], p[3][j]);
            *(float4*)&Ps[(c0 + j) * ST + r0] = pj;
        }
        __syncthreads();

        // ---- O = alpha*O + P V ----
#pragma unroll
        for (int i = 0; i < 4; i++) {
            u64 a2 = pack_dup(alpha[i]);
            fmul2(o2[i][0], a2);
            fmul2(o2[i][1], a2);
        }
#pragma unroll 8
        for (int kk = 0; kk < BK; kk++) {
            float4 pv = *(const float4*)&Ps[kk * ST + r0];   // broadcast in group
            ulonglong2 vvp = *(const ulonglong2*)&Vs[kk * ST + c0];
            u64 p0 = pack_dup(pv.x), p1 = pack_dup(pv.y);
            u64 p2 = pack_dup(pv.z), p3 = pack_dup(pv.w);
            ffma2(o2[0][0], p0, vvp.x); ffma2(o2[0][1], p0, vvp.y);
            ffma2(o2[1][0], p1, vvp.x); ffma2(o2[1][1], p1, vvp.y);
            ffma2(o2[2][0], p2, vvp.x); ffma2(o2[2][1], p2, vvp.y);
            ffma2(o2[3][0], p3, vvp.x); ffma2(o2[3][1], p3, vvp.y);
        }
    }

    // Epilogue: normalize, apply query mask, write [B, Sq, H*64]
#pragma unroll
    for (int i = 0; i < 4; i++) {
        int gq = qb * BQ + r0 + i;
        float f = (1.0f / l_run[i]) * qmask[(size_t)b * SEQ + gq];
        float2 lo = unpack2(o2[i][0]);
        float2 hi = unpack2(o2[i][1]);
        float4 v = make_float4(lo.x * f, lo.y * f, hi.x * f, hi.y * f);
        *(float4*)&out[((size_t)b * SEQ + gq) * (HEADS * DHEAD) + h * DHEAD + c0] = v;
    }
}

// ---------------------------------------------------------------------------
// Launch
// ---------------------------------------------------------------------------
extern "C" void kernel_launch(void* const* d_in, const int* in_sizes, int n_in,
                              void* d_out, int out_size)
{
    const float* q     = (const float*)d_in[0];
    const float* k     = (const float*)d_in[1];
    const float* v     = (const float*)d_in[2];
    const float* vmask = (const float*)d_in[3];
    const float* qmask = (const float*)d_in[4];
    const float* Wq    = (const float*)d_in[5];
    const float* Wk    = (const float*)d_in[6];
    const float* Wv    = (const float*)d_in[7];
    float* out = (float*)d_out;

    float *qp, *kp, *vp;
    cudaGetSymbolAddress((void**)&qp, g_Qp);
    cudaGetSymbolAddress((void**)&kp, g_Kp);
    cudaGetSymbolAddress((void**)&vp, g_Vp);

    dim3 gg(DMODEL / 128, (BATCH * SEQ) / 128, 3);   // (8, 64, 3)
    proj_gemm3<<<gg, 256>>>(q, k, v, Wq, Wk, Wv, qp, kp, vp);

    const int smem_bytes = (4 * BQ * ST + BK) * (int)sizeof(float); // ~69.9 KB
    cudaFuncSetAttribute(attn_kernel, cudaFuncAttributeMaxDynamicSharedMemorySize,
                         smem_bytes);
    dim3 ga(SEQ / BQ, HEADS, BATCH);                 // (32, 16, 4)
    attn_kernel<<<ga, 256, smem_bytes>>>(qp, kp, vp, vmask, qmask, out);
}